// round 11
// baseline (speedup 1.0000x reference)
#include <cuda_runtime.h>
#include <cuda_fp16.h>
#include <cstdint>

// Problem constants
constexpr int BB  = 4;
constexpr int SS  = 2048;
constexpr int HH  = 1024;
constexpr int NH  = 16;
constexpr int HD  = 64;
constexpr int SPL = 8;

// Scratch (static device globals — allowed)
__device__ float g_Gpart[SPL][BB * NH][HD][HD];  // 8 MB
__device__ __half g_Vt[BB][HH][HH];              // 8.4 MB: Vt[n][k]
__device__ __half g_Xh[BB][SS][HH];              // 16.8 MB: x rounded to fp16

// ---------------------------------------------------------------------------
// helpers
// ---------------------------------------------------------------------------
__device__ __forceinline__ void mma16816(float* c, const uint32_t* a, const uint32_t* b) {
    asm volatile(
        "mma.sync.aligned.m16n8k16.row.col.f32.f16.f16.f32 "
        "{%0,%1,%2,%3}, {%4,%5,%6,%7}, {%8,%9}, {%0,%1,%2,%3};"
        : "+f"(c[0]), "+f"(c[1]), "+f"(c[2]), "+f"(c[3])
        : "r"(a[0]), "r"(a[1]), "r"(a[2]), "r"(a[3]), "r"(b[0]), "r"(b[1]));
}
__device__ __forceinline__ void ldsm4(uint32_t* r, uint32_t saddr) {
    asm volatile("ldmatrix.sync.aligned.m8n8.x4.shared.b16 {%0,%1,%2,%3}, [%4];"
                 : "=r"(r[0]), "=r"(r[1]), "=r"(r[2]), "=r"(r[3]) : "r"(saddr));
}
__device__ __forceinline__ void ldsm4t(uint32_t* r, uint32_t saddr) {
    asm volatile("ldmatrix.sync.aligned.m8n8.x4.trans.shared.b16 {%0,%1,%2,%3}, [%4];"
                 : "=r"(r[0]), "=r"(r[1]), "=r"(r[2]), "=r"(r[3]) : "r"(saddr));
}
__device__ __forceinline__ void cpasync16(uint32_t dst, const void* src) {
    asm volatile("cp.async.cg.shared.global [%0], [%1], 16;" :: "r"(dst), "l"(src));
}
#define CP_COMMIT() asm volatile("cp.async.commit_group;" ::: "memory")
#define CP_WAIT2()  asm volatile("cp.async.wait_group 2;" ::: "memory")

// ---------------------------------------------------------------------------
// Kernel 1: partial Gram via HMMA (hi/lo split, 3 passes) + emit g_Xh (fp16 hi)
//   per-batch launch: grid (NH, SPL)
// ---------------------------------------------------------------------------
constexpr int GP = 72;   // smem row pitch (halves)

__global__ void __launch_bounds__(256) gram_mma(const float* __restrict__ x, int b) {
    __shared__ __align__(16) __half Xhs[64][GP];
    __shared__ __align__(16) __half Xls[64][GP];

    const int h     = blockIdx.x;
    const int chunk = blockIdx.y;
    const int bh    = b * NH + h;
    const float* Xb = x + (size_t)b * SS * HH + h * HD;
    const int s0 = chunk * (SS / SPL);

    const int t = threadIdx.x, lane = t & 31, w = t >> 5;
    const int lr8 = lane & 7, g = lane >> 3;

    const int m0 = (w & 3) * 16;
    const int nb = (w >> 2) * 32;

    float acc[4][4] = {};

    uint32_t hbase = (uint32_t)__cvta_generic_to_shared(&Xhs[0][0]);
    uint32_t lbase = (uint32_t)__cvta_generic_to_shared(&Xls[0][0]);
    const uint32_t aoff = (uint32_t)((((g & 2) ? 8 : 0) + lr8) * GP + m0 + ((g & 1) ? 8 : 0)) * 2;
    const uint32_t boff0 = (uint32_t)((((g & 1) ? 8 : 0) + lr8) * GP + nb + ((g & 2) ? 8 : 0)) * 2;
    const uint32_t boff1 = boff0 + 16 * 2;

    for (int sub = 0; sub < 4; ++sub) {
#pragma unroll
        for (int q = 0; q < 4; ++q) {
            int idx = q * 256 + t;
            int r = idx >> 4, c = idx & 15;
            int srow = s0 + sub * 64 + r;
            float4 v = *reinterpret_cast<const float4*>(&Xb[(size_t)srow * HH + c * 4]);
            __half hx = __float2half_rn(v.x), hy = __float2half_rn(v.y);
            __half hz = __float2half_rn(v.z), hw = __float2half_rn(v.w);
            __half lx = __float2half_rn(v.x - __half2float(hx));
            __half ly = __float2half_rn(v.y - __half2float(hy));
            __half lz = __float2half_rn(v.z - __half2float(hz));
            __half lw = __float2half_rn(v.w - __half2float(hw));
            __half2 p0 = __halves2half2(hx, hy), p1 = __halves2half2(hz, hw);
            __half2* dh = reinterpret_cast<__half2*>(&Xhs[r][c * 4]);
            dh[0] = p0; dh[1] = p1;
            __half2* dl = reinterpret_cast<__half2*>(&Xls[r][c * 4]);
            dl[0] = __halves2half2(lx, ly); dl[1] = __halves2half2(lz, lw);
            __half2* gx = reinterpret_cast<__half2*>(&g_Xh[b][srow][h * HD + c * 4]);
            gx[0] = p0; gx[1] = p1;
        }
        __syncthreads();

#pragma unroll
        for (int kk = 0; kk < 64; kk += 16) {
            const uint32_t kb = (uint32_t)(kk * GP * 2);
            uint32_t ah[4], al[4], bh0[4], bh1[4], bl0[4], bl1[4];
            ldsm4t(ah,  hbase + kb + aoff);
            ldsm4t(al,  lbase + kb + aoff);
            ldsm4t(bh0, hbase + kb + boff0);
            ldsm4t(bh1, hbase + kb + boff1);
            ldsm4t(bl0, lbase + kb + boff0);
            ldsm4t(bl1, lbase + kb + boff1);
#pragma unroll
            for (int nt = 0; nt < 4; ++nt) {
                const uint32_t* bh_ = (nt < 2) ? bh0 : bh1;
                const uint32_t* bl_ = (nt < 2) ? bl0 : bl1;
                uint32_t bhf[2] = {bh_[(nt & 1) * 2], bh_[(nt & 1) * 2 + 1]};
                uint32_t blf[2] = {bl_[(nt & 1) * 2], bl_[(nt & 1) * 2 + 1]};
                mma16816(acc[nt], ah, bhf);
                mma16816(acc[nt], ah, blf);
                mma16816(acc[nt], al, bhf);
            }
        }
        __syncthreads();
    }

    const int lr = lane >> 2, lc = (lane & 3) * 2;
#pragma unroll
    for (int nt = 0; nt < 4; ++nt) {
        int n = nb + nt * 8 + lc;
        *reinterpret_cast<float2*>(&g_Gpart[chunk][bh][m0 + lr][n]) =
            make_float2(acc[nt][0], acc[nt][1]);
        *reinterpret_cast<float2*>(&g_Gpart[chunk][bh][m0 + lr + 8][n]) =
            make_float2(acc[nt][2], acc[nt][3]);
    }
}

// ---------------------------------------------------------------------------
// Kernel 2: combine via HMMA -> Vt[n][k] fp16 ; per-batch: grid (NH, 4)
// ---------------------------------------------------------------------------
__global__ void __launch_bounds__(256) combine_mma(const float* __restrict__ W, int b) {
    __shared__ __align__(16) __half Gh[64][GP], Gl[64][GP];
    __shared__ __align__(16) __half Wh[64][GP], Wl[64][GP];

    const int h = blockIdx.x, ic = blockIdx.y;
    const int bh = b * NH + h;
    const int t = threadIdx.x, lane = t & 31, w = t >> 5;
    const int m0 = (w & 1) * 32;
    const int n0 = (w >> 1) * 16;

    for (int idx = t; idx < 64 * 64; idx += 256) {
        int e = idx >> 6, d = idx & 63;
        float s = 0.f;
#pragma unroll
        for (int p = 0; p < SPL; ++p) s += g_Gpart[p][bh][e][d];
        __half hi = __float2half_rn(s);
        Gh[e][d] = hi;
        Gl[e][d] = __float2half_rn(s - __half2float(hi));
    }

    const int lr8 = lane & 7, g = lane >> 3;
    const uint32_t ghb = (uint32_t)__cvta_generic_to_shared(&Gh[0][0]);
    const uint32_t glb = (uint32_t)__cvta_generic_to_shared(&Gl[0][0]);
    const uint32_t whb = (uint32_t)__cvta_generic_to_shared(&Wh[0][0]);
    const uint32_t wlb = (uint32_t)__cvta_generic_to_shared(&Wl[0][0]);
    const uint32_t aoff0 = (uint32_t)((((g & 2) ? 8 : 0) + lr8) * GP + m0 + ((g & 1) ? 8 : 0)) * 2;
    const uint32_t aoff1 = aoff0 + 16 * 2;
    const uint32_t boff  = (uint32_t)((((g & 1) ? 8 : 0) + lr8) * GP + n0 + ((g & 2) ? 8 : 0)) * 2;

    const int lr = lane >> 2, lc = (lane & 3) * 2;
    __syncthreads();

    for (int sub = 0; sub < 4; ++sub) {
        const int i0 = ic * 256 + sub * 64;
        for (int idx = t; idx < 64 * 64; idx += 256) {
            int e = idx >> 6, i = idx & 63;
            float wv = W[(size_t)(h * HD + e) * HH + i0 + i] * 8192.f;
            __half hi = __float2half_rn(wv);
            Wh[e][i] = hi;
            Wl[e][i] = __float2half_rn(wv - __half2float(hi));
        }
        __syncthreads();

        float acc[2][2][4] = {};
#pragma unroll
        for (int kk = 0; kk < 64; kk += 16) {
            const uint32_t kb = (uint32_t)(kk * GP * 2);
            uint32_t a0h[4], a0l[4], a1h[4], a1l[4], bwh[4], bwl[4];
            ldsm4t(a0h, ghb + kb + aoff0);
            ldsm4t(a0l, glb + kb + aoff0);
            ldsm4t(a1h, ghb + kb + aoff1);
            ldsm4t(a1l, glb + kb + aoff1);
            ldsm4t(bwh, whb + kb + boff);
            ldsm4t(bwl, wlb + kb + boff);
#pragma unroll
            for (int nt = 0; nt < 2; ++nt) {
                uint32_t bhf[2] = {bwh[nt * 2], bwh[nt * 2 + 1]};
                uint32_t blf[2] = {bwl[nt * 2], bwl[nt * 2 + 1]};
                mma16816(acc[0][nt], a0h, bhf);
                mma16816(acc[0][nt], a0h, blf);
                mma16816(acc[0][nt], a0l, bhf);
                mma16816(acc[1][nt], a1h, bhf);
                mma16816(acc[1][nt], a1h, blf);
                mma16816(acc[1][nt], a1l, bhf);
            }
        }

        const float is = 1.f / 8192.f;
#pragma unroll
        for (int mt = 0; mt < 2; ++mt)
#pragma unroll
            for (int nt = 0; nt < 2; ++nt) {
                int d = m0 + mt * 16 + lr;
                int gi = i0 + n0 + nt * 8 + lc;
                __half2 v01 = __floats2half2_rn(acc[mt][nt][0] * is, acc[mt][nt][1] * is);
                __half2 v23 = __floats2half2_rn(acc[mt][nt][2] * is, acc[mt][nt][3] * is);
                *reinterpret_cast<__half2*>(&g_Vt[b][h * HD + d][gi]) = v01;
                *reinterpret_cast<__half2*>(&g_Vt[b][h * HD + d + 8][gi]) = v23;
            }
        __syncthreads();
    }
}

// ---------------------------------------------------------------------------
// Kernel 3: pure-fp16 HMMA GEMM (R6 config) ; per-batch: grid (8, 16)
//   4 warps x (64x64), CTA 128x128, KT=32, 4-stage ring, issue-early
// ---------------------------------------------------------------------------
constexpr int KT    = 32;
constexpr int PITCH = 40;
constexpr int OPH   = 128 * PITCH;
constexpr int STH   = 2 * OPH;
constexpr int NST   = 4;
constexpr int GEMM_SMEM = NST * STH * 2;  // 81920 bytes

__global__ void __launch_bounds__(128, 2) gemm_mma(float* __restrict__ Out, int b) {
    extern __shared__ __half sm[];
    const int t = threadIdx.x, lane = t & 31, wid = t >> 5;
    const int crow = blockIdx.y * 128, ccol = blockIdx.x * 128;
    const __half* Ag = &g_Xh[b][0][0];
    const __half* Bg = &g_Vt[b][0][0];

    const uint32_t smu = (uint32_t)__cvta_generic_to_shared(sm);

    const int m0 = (wid & 1) * 64;
    const int n0 = (wid >> 1) * 64;
    const int lr8 = lane & 7, g = lane >> 3;

    uint32_t aoffb[4], boffb[4];
#pragma unroll
    for (int mt = 0; mt < 4; ++mt)
        aoffb[mt] = (uint32_t)(((m0 + mt * 16 + ((g & 1) ? 8 : 0) + lr8) * PITCH
                                + ((g & 2) ? 8 : 0)) * 2);
#pragma unroll
    for (int j = 0; j < 4; ++j)
        boffb[j] = (uint32_t)(((n0 + j * 16 + ((g & 1) ? 8 : 0) + lr8) * PITCH
                               + ((g & 2) ? 8 : 0)) * 2);

    const int cpr = t >> 2, cpc = t & 3;
    const __half* aSrc = Ag + (size_t)(crow + cpr) * HH + cpc * 8;
    const __half* bSrc = Bg + (size_t)(ccol + cpr) * HH + cpc * 8;
    const uint32_t aDst = smu + (uint32_t)((cpr * PITCH + cpc * 8) * 2);
    const uint32_t bDst = aDst + OPH * 2;

    float acc[4][8][4];
#pragma unroll
    for (int mt = 0; mt < 4; ++mt)
#pragma unroll
        for (int nt = 0; nt < 8; ++nt)
#pragma unroll
            for (int j = 0; j < 4; ++j) acc[mt][nt][j] = 0.f;

#define ISSUE_STAGE(st, buf)                                                    \
    do {                                                                        \
        const int k0 = (st) * KT;                                               \
        const uint32_t sb = (uint32_t)((buf) * STH * 2);                        \
        _Pragma("unroll")                                                       \
        for (int q = 0; q < 4; ++q) {                                           \
            cpasync16(aDst + sb + q * 32 * PITCH * 2,                           \
                      aSrc + (size_t)q * 32 * HH + k0);                         \
            cpasync16(bDst + sb + q * 32 * PITCH * 2,                           \
                      bSrc + (size_t)q * 32 * HH + k0);                         \
        }                                                                       \
    } while (0)

    ISSUE_STAGE(0, 0); CP_COMMIT();
    ISSUE_STAGE(1, 1); CP_COMMIT();
    ISSUE_STAGE(2, 2); CP_COMMIT();

    const int NSTAGES = HH / KT;   // 32
    for (int st = 0; st < NSTAGES; ++st) {
        CP_WAIT2();
        __syncthreads();

        // issue-early: buffer (st+3)&3 == (st-1)&3; the sync above proves all
        // iter st-1 reads of that buffer completed.
        if (st + 3 < NSTAGES) ISSUE_STAGE(st + 3, (st + 3) & 3);
        CP_COMMIT();

        const uint32_t baseA = smu + (uint32_t)((st & 3) * STH * 2);
        const uint32_t baseB = baseA + OPH * 2;
#pragma unroll
        for (int kk = 0; kk < KT; kk += 16) {
            const uint32_t kb = (uint32_t)(kk * 2);
            uint32_t af[4][4], bf[4][4];
#pragma unroll
            for (int mt = 0; mt < 4; ++mt) ldsm4(af[mt], baseA + aoffb[mt] + kb);
#pragma unroll
            for (int j = 0; j < 4; ++j)    ldsm4(bf[j],  baseB + boffb[j] + kb);
#pragma unroll
            for (int mt = 0; mt < 4; ++mt)
#pragma unroll
                for (int nt = 0; nt < 8; ++nt) {
                    uint32_t bb[2] = {bf[nt >> 1][(nt & 1) ? 1 : 0],
                                      bf[nt >> 1][(nt & 1) ? 3 : 2]};
                    mma16816(acc[mt][nt], af[mt], bb);
                }
        }
    }

    // Epilogue
    const int lr = lane >> 2, lc = (lane & 3) * 2;
    float* C = Out + (size_t)b * SS * HH;
#pragma unroll
    for (int mt = 0; mt < 4; ++mt)
#pragma unroll
        for (int nt = 0; nt < 8; ++nt) {
            int r = crow + m0 + mt * 16 + lr;
            int c = ccol + n0 + nt * 8 + lc;
            *reinterpret_cast<float2*>(&C[(size_t)r * HH + c]) =
                make_float2(acc[mt][nt][0], acc[mt][nt][1]);
            *reinterpret_cast<float2*>(&C[(size_t)(r + 8) * HH + c]) =
                make_float2(acc[mt][nt][2], acc[mt][nt][3]);
        }
}

// ---------------------------------------------------------------------------
// Host: per-batch stream pipelining (fork/join via events, capture-safe).
// Streams/events created once in a static constructor (before harness
// memory checkpoints; nothing allocated inside kernel_launch / the graph).
// ---------------------------------------------------------------------------
namespace {
struct LaunchRes {
    cudaStream_t s[BB];
    cudaEvent_t  root;
    cudaEvent_t  done[BB];
    LaunchRes() {
        for (int i = 0; i < BB; ++i)
            cudaStreamCreateWithFlags(&s[i], cudaStreamNonBlocking);
        cudaEventCreateWithFlags(&root, cudaEventDisableTiming);
        for (int i = 0; i < BB; ++i)
            cudaEventCreateWithFlags(&done[i], cudaEventDisableTiming);
        cudaFuncSetAttribute(gemm_mma, cudaFuncAttributeMaxDynamicSharedMemorySize,
                             GEMM_SMEM);
    }
};
LaunchRes g_res;   // constructed at load time
}

extern "C" void kernel_launch(void* const* d_in, const int* in_sizes, int n_in,
                              void* d_out, int out_size) {
    const float* x = (const float*)d_in[0];   // [4,2048,1024]
    const float* W = (const float*)d_in[1];   // [1024,1024]
    float* out = (float*)d_out;               // [4,2048,1024]

    cudaEventRecord(g_res.root, 0);
    for (int b = 0; b < BB; ++b) {
        cudaStream_t s = g_res.s[b];
        cudaStreamWaitEvent(s, g_res.root, 0);
        gram_mma<<<dim3(NH, SPL), 256, 0, s>>>(x, b);
        combine_mma<<<dim3(NH, 4), 256, 0, s>>>(W, b);
        gemm_mma<<<dim3(HH / 128, SS / 128), 128, GEMM_SMEM, s>>>(out, b);
        cudaEventRecord(g_res.done[b], s);
        cudaStreamWaitEvent(0, g_res.done[b], 0);
    }
}

// round 16
// speedup vs baseline: 1.0274x; 1.0274x over previous
#include <cuda_runtime.h>
#include <cuda_fp16.h>
#include <cstdint>

// Problem constants
constexpr int BB  = 4;
constexpr int SS  = 2048;
constexpr int HH  = 1024;
constexpr int NH  = 16;
constexpr int HD  = 64;
constexpr int SPL = 8;

// Scratch (static device globals — allowed)
__device__ float g_Gpart[SPL][BB * NH][HD][HD];  // 8 MB
__device__ __half g_Vt[BB][HH][HH];              // 8.4 MB: Vt[n][k]
__device__ __half g_Xh[BB][SS][HH];              // 16.8 MB: x rounded to fp16

// ---------------------------------------------------------------------------
// helpers
// ---------------------------------------------------------------------------
__device__ __forceinline__ void mma16816(float* c, const uint32_t* a, const uint32_t* b) {
    asm volatile(
        "mma.sync.aligned.m16n8k16.row.col.f32.f16.f16.f32 "
        "{%0,%1,%2,%3}, {%4,%5,%6,%7}, {%8,%9}, {%0,%1,%2,%3};"
        : "+f"(c[0]), "+f"(c[1]), "+f"(c[2]), "+f"(c[3])
        : "r"(a[0]), "r"(a[1]), "r"(a[2]), "r"(a[3]), "r"(b[0]), "r"(b[1]));
}
__device__ __forceinline__ void ldsm4(uint32_t* r, uint32_t saddr) {
    asm volatile("ldmatrix.sync.aligned.m8n8.x4.shared.b16 {%0,%1,%2,%3}, [%4];"
                 : "=r"(r[0]), "=r"(r[1]), "=r"(r[2]), "=r"(r[3]) : "r"(saddr));
}
__device__ __forceinline__ void ldsm4t(uint32_t* r, uint32_t saddr) {
    asm volatile("ldmatrix.sync.aligned.m8n8.x4.trans.shared.b16 {%0,%1,%2,%3}, [%4];"
                 : "=r"(r[0]), "=r"(r[1]), "=r"(r[2]), "=r"(r[3]) : "r"(saddr));
}
__device__ __forceinline__ void cpasync16(uint32_t dst, const void* src) {
    asm volatile("cp.async.cg.shared.global [%0], [%1], 16;" :: "r"(dst), "l"(src));
}
#define CP_COMMIT() asm volatile("cp.async.commit_group;" ::: "memory")
#define CP_WAIT2()  asm volatile("cp.async.wait_group 2;" ::: "memory")

// ---------------------------------------------------------------------------
// Kernel 1: partial Gram via HMMA (hi/lo split, 3 passes) + emit g_Xh (fp16 hi)
//   batched: grid (BB*NH, SPL). LDGs batched into regs first (MLP=4).
// ---------------------------------------------------------------------------
constexpr int GP = 72;   // smem row pitch (halves)

__global__ void __launch_bounds__(256) gram_mma(const float* __restrict__ x) {
    __shared__ __align__(16) __half Xhs[64][GP];
    __shared__ __align__(16) __half Xls[64][GP];

    const int bh    = blockIdx.x;
    const int chunk = blockIdx.y;
    const int b = bh / NH, h = bh % NH;
    const float* Xb = x + (size_t)b * SS * HH + h * HD;
    const int s0 = chunk * (SS / SPL);

    const int t = threadIdx.x, lane = t & 31, w = t >> 5;
    const int lr8 = lane & 7, g = lane >> 3;

    const int m0 = (w & 3) * 16;
    const int nb = (w >> 2) * 32;

    float acc[4][4] = {};

    uint32_t hbase = (uint32_t)__cvta_generic_to_shared(&Xhs[0][0]);
    uint32_t lbase = (uint32_t)__cvta_generic_to_shared(&Xls[0][0]);
    const uint32_t aoff = (uint32_t)((((g & 2) ? 8 : 0) + lr8) * GP + m0 + ((g & 1) ? 8 : 0)) * 2;
    const uint32_t boff0 = (uint32_t)((((g & 1) ? 8 : 0) + lr8) * GP + nb + ((g & 2) ? 8 : 0)) * 2;
    const uint32_t boff1 = boff0 + 16 * 2;

    const int ldr = t >> 4, ldc = t & 15;   // row 0..15, 16B col 0..15

    for (int sub = 0; sub < 4; ++sub) {
        // batch all 4 global loads first (MLP=4), then convert+store
        float4 vv[4];
#pragma unroll
        for (int q = 0; q < 4; ++q) {
            int srow = s0 + sub * 64 + q * 16 + ldr;
            vv[q] = *reinterpret_cast<const float4*>(&Xb[(size_t)srow * HH + ldc * 4]);
        }
#pragma unroll
        for (int q = 0; q < 4; ++q) {
            int r = q * 16 + ldr;
            int srow = s0 + sub * 64 + r;
            float4 v = vv[q];
            __half hx = __float2half_rn(v.x), hy = __float2half_rn(v.y);
            __half hz = __float2half_rn(v.z), hw = __float2half_rn(v.w);
            __half lx = __float2half_rn(v.x - __half2float(hx));
            __half ly = __float2half_rn(v.y - __half2float(hy));
            __half lz = __float2half_rn(v.z - __half2float(hz));
            __half lw = __float2half_rn(v.w - __half2float(hw));
            __half2 p0 = __halves2half2(hx, hy), p1 = __halves2half2(hz, hw);
            __half2* dh = reinterpret_cast<__half2*>(&Xhs[r][ldc * 4]);
            dh[0] = p0; dh[1] = p1;
            __half2* dl = reinterpret_cast<__half2*>(&Xls[r][ldc * 4]);
            dl[0] = __halves2half2(lx, ly); dl[1] = __halves2half2(lz, lw);
            __half2* gx = reinterpret_cast<__half2*>(&g_Xh[b][srow][h * HD + ldc * 4]);
            gx[0] = p0; gx[1] = p1;
        }
        __syncthreads();

#pragma unroll
        for (int kk = 0; kk < 64; kk += 16) {
            const uint32_t kb = (uint32_t)(kk * GP * 2);
            uint32_t ah[4], al[4], bh0[4], bh1[4], bl0[4], bl1[4];
            ldsm4t(ah,  hbase + kb + aoff);
            ldsm4t(al,  lbase + kb + aoff);
            ldsm4t(bh0, hbase + kb + boff0);
            ldsm4t(bh1, hbase + kb + boff1);
            ldsm4t(bl0, lbase + kb + boff0);
            ldsm4t(bl1, lbase + kb + boff1);
#pragma unroll
            for (int nt = 0; nt < 4; ++nt) {
                const uint32_t* bh_ = (nt < 2) ? bh0 : bh1;
                const uint32_t* bl_ = (nt < 2) ? bl0 : bl1;
                uint32_t bhf[2] = {bh_[(nt & 1) * 2], bh_[(nt & 1) * 2 + 1]};
                uint32_t blf[2] = {bl_[(nt & 1) * 2], bl_[(nt & 1) * 2 + 1]};
                mma16816(acc[nt], ah, bhf);
                mma16816(acc[nt], ah, blf);
                mma16816(acc[nt], al, bhf);
            }
        }
        __syncthreads();
    }

    const int lr = lane >> 2, lc = (lane & 3) * 2;
#pragma unroll
    for (int nt = 0; nt < 4; ++nt) {
        int n = nb + nt * 8 + lc;
        *reinterpret_cast<float2*>(&g_Gpart[chunk][bh][m0 + lr][n]) =
            make_float2(acc[nt][0], acc[nt][1]);
        *reinterpret_cast<float2*>(&g_Gpart[chunk][bh][m0 + lr + 8][n]) =
            make_float2(acc[nt][2], acc[nt][3]);
    }
}

// ---------------------------------------------------------------------------
// Kernel 2: combine via HMMA -> Vt[n][k] fp16 ; batched: grid (BB*NH, 4)
// ---------------------------------------------------------------------------
__global__ void __launch_bounds__(256) combine_mma(const float* __restrict__ W) {
    __shared__ __align__(16) __half Gh[64][GP], Gl[64][GP];
    __shared__ __align__(16) __half Wh[64][GP], Wl[64][GP];

    const int bh = blockIdx.x, ic = blockIdx.y;
    const int b = bh / NH, h = bh % NH;
    const int t = threadIdx.x, lane = t & 31, w = t >> 5;
    const int m0 = (w & 1) * 32;
    const int n0 = (w >> 1) * 16;

    for (int idx = t; idx < 64 * 64; idx += 256) {
        int e = idx >> 6, d = idx & 63;
        float s = 0.f;
#pragma unroll
        for (int p = 0; p < SPL; ++p) s += g_Gpart[p][bh][e][d];
        __half hi = __float2half_rn(s);
        Gh[e][d] = hi;
        Gl[e][d] = __float2half_rn(s - __half2float(hi));
    }

    const int lr8 = lane & 7, g = lane >> 3;
    const uint32_t ghb = (uint32_t)__cvta_generic_to_shared(&Gh[0][0]);
    const uint32_t glb = (uint32_t)__cvta_generic_to_shared(&Gl[0][0]);
    const uint32_t whb = (uint32_t)__cvta_generic_to_shared(&Wh[0][0]);
    const uint32_t wlb = (uint32_t)__cvta_generic_to_shared(&Wl[0][0]);
    const uint32_t aoff0 = (uint32_t)((((g & 2) ? 8 : 0) + lr8) * GP + m0 + ((g & 1) ? 8 : 0)) * 2;
    const uint32_t aoff1 = aoff0 + 16 * 2;
    const uint32_t boff  = (uint32_t)((((g & 1) ? 8 : 0) + lr8) * GP + n0 + ((g & 2) ? 8 : 0)) * 2;

    const int lr = lane >> 2, lc = (lane & 3) * 2;
    __syncthreads();

    for (int sub = 0; sub < 4; ++sub) {
        const int i0 = ic * 256 + sub * 64;
        for (int idx = t; idx < 64 * 64; idx += 256) {
            int e = idx >> 6, i = idx & 63;
            float wv = W[(size_t)(h * HD + e) * HH + i0 + i] * 8192.f;
            __half hi = __float2half_rn(wv);
            Wh[e][i] = hi;
            Wl[e][i] = __float2half_rn(wv - __half2float(hi));
        }
        __syncthreads();

        float acc[2][2][4] = {};
#pragma unroll
        for (int kk = 0; kk < 64; kk += 16) {
            const uint32_t kb = (uint32_t)(kk * GP * 2);
            uint32_t a0h[4], a0l[4], a1h[4], a1l[4], bwh[4], bwl[4];
            ldsm4t(a0h, ghb + kb + aoff0);
            ldsm4t(a0l, glb + kb + aoff0);
            ldsm4t(a1h, ghb + kb + aoff1);
            ldsm4t(a1l, glb + kb + aoff1);
            ldsm4t(bwh, whb + kb + boff);
            ldsm4t(bwl, wlb + kb + boff);
#pragma unroll
            for (int nt = 0; nt < 2; ++nt) {
                uint32_t bhf[2] = {bwh[nt * 2], bwh[nt * 2 + 1]};
                uint32_t blf[2] = {bwl[nt * 2], bwl[nt * 2 + 1]};
                mma16816(acc[0][nt], a0h, bhf);
                mma16816(acc[0][nt], a0h, blf);
                mma16816(acc[0][nt], a0l, bhf);
                mma16816(acc[1][nt], a1h, bhf);
                mma16816(acc[1][nt], a1h, blf);
                mma16816(acc[1][nt], a1l, bhf);
            }
        }

        const float is = 1.f / 8192.f;
#pragma unroll
        for (int mt = 0; mt < 2; ++mt)
#pragma unroll
            for (int nt = 0; nt < 2; ++nt) {
                int d = m0 + mt * 16 + lr;
                int gi = i0 + n0 + nt * 8 + lc;
                __half2 v01 = __floats2half2_rn(acc[mt][nt][0] * is, acc[mt][nt][1] * is);
                __half2 v23 = __floats2half2_rn(acc[mt][nt][2] * is, acc[mt][nt][3] * is);
                *reinterpret_cast<__half2*>(&g_Vt[b][h * HD + d][gi]) = v01;
                *reinterpret_cast<__half2*>(&g_Vt[b][h * HD + d + 8][gi]) = v23;
            }
        __syncthreads();
    }
}

// ---------------------------------------------------------------------------
// Kernel 3: pure-fp16 HMMA GEMM — R6 config + issue-early; batched grid
//   4 warps x (64x64), CTA 128x128, KT=32, 4-stage cp.async ring
// ---------------------------------------------------------------------------
constexpr int KT    = 32;
constexpr int PITCH = 40;
constexpr int OPH   = 128 * PITCH;
constexpr int STH   = 2 * OPH;
constexpr int NST   = 4;
constexpr int GEMM_SMEM = NST * STH * 2;  // 81920 bytes

__global__ void __launch_bounds__(128, 2) gemm_mma(float* __restrict__ Out) {
    extern __shared__ __half sm[];
    const int t = threadIdx.x, lane = t & 31, wid = t >> 5;
    const int b = blockIdx.z;
    const int crow = blockIdx.y * 128, ccol = blockIdx.x * 128;
    const __half* Ag = &g_Xh[b][0][0];
    const __half* Bg = &g_Vt[b][0][0];

    const uint32_t smu = (uint32_t)__cvta_generic_to_shared(sm);

    const int m0 = (wid & 1) * 64;
    const int n0 = (wid >> 1) * 64;
    const int lr8 = lane & 7, g = lane >> 3;

    uint32_t aoffb[4], boffb[4];
#pragma unroll
    for (int mt = 0; mt < 4; ++mt)
        aoffb[mt] = (uint32_t)(((m0 + mt * 16 + ((g & 1) ? 8 : 0) + lr8) * PITCH
                                + ((g & 2) ? 8 : 0)) * 2);
#pragma unroll
    for (int j = 0; j < 4; ++j)
        boffb[j] = (uint32_t)(((n0 + j * 16 + ((g & 1) ? 8 : 0) + lr8) * PITCH
                               + ((g & 2) ? 8 : 0)) * 2);

    const int cpr = t >> 2, cpc = t & 3;
    const __half* aSrc = Ag + (size_t)(crow + cpr) * HH + cpc * 8;
    const __half* bSrc = Bg + (size_t)(ccol + cpr) * HH + cpc * 8;
    const uint32_t aDst = smu + (uint32_t)((cpr * PITCH + cpc * 8) * 2);
    const uint32_t bDst = aDst + OPH * 2;

    float acc[4][8][4];
#pragma unroll
    for (int mt = 0; mt < 4; ++mt)
#pragma unroll
        for (int nt = 0; nt < 8; ++nt)
#pragma unroll
            for (int j = 0; j < 4; ++j) acc[mt][nt][j] = 0.f;

#define ISSUE_STAGE(st, buf)                                                    \
    do {                                                                        \
        const int k0 = (st) * KT;                                               \
        const uint32_t sb = (uint32_t)((buf) * STH * 2);                        \
        _Pragma("unroll")                                                       \
        for (int q = 0; q < 4; ++q) {                                           \
            cpasync16(aDst + sb + q * 32 * PITCH * 2,                           \
                      aSrc + (size_t)q * 32 * HH + k0);                         \
            cpasync16(bDst + sb + q * 32 * PITCH * 2,                           \
                      bSrc + (size_t)q * 32 * HH + k0);                         \
        }                                                                       \
    } while (0)

    ISSUE_STAGE(0, 0); CP_COMMIT();
    ISSUE_STAGE(1, 1); CP_COMMIT();
    ISSUE_STAGE(2, 2); CP_COMMIT();

    const int NSTAGES = HH / KT;   // 32
    for (int st = 0; st < NSTAGES; ++st) {
        CP_WAIT2();
        __syncthreads();

        // issue-early: buffer (st+3)&3 == (st-1)&3; the sync above proves all
        // iter st-1 reads of that buffer completed.
        if (st + 3 < NSTAGES) ISSUE_STAGE(st + 3, (st + 3) & 3);
        CP_COMMIT();

        const uint32_t baseA = smu + (uint32_t)((st & 3) * STH * 2);
        const uint32_t baseB = baseA + OPH * 2;
#pragma unroll
        for (int kk = 0; kk < KT; kk += 16) {
            const uint32_t kb = (uint32_t)(kk * 2);
            uint32_t af[4][4], bf[4][4];
#pragma unroll
            for (int mt = 0; mt < 4; ++mt) ldsm4(af[mt], baseA + aoffb[mt] + kb);
#pragma unroll
            for (int j = 0; j < 4; ++j)    ldsm4(bf[j],  baseB + boffb[j] + kb);
#pragma unroll
            for (int mt = 0; mt < 4; ++mt)
#pragma unroll
                for (int nt = 0; nt < 8; ++nt) {
                    uint32_t bb[2] = {bf[nt >> 1][(nt & 1) ? 1 : 0],
                                      bf[nt >> 1][(nt & 1) ? 3 : 2]};
                    mma16816(acc[mt][nt], af[mt], bb);
                }
        }
    }

    // Epilogue
    const int lr = lane >> 2, lc = (lane & 3) * 2;
    float* C = Out + (size_t)b * SS * HH;
#pragma unroll
    for (int mt = 0; mt < 4; ++mt)
#pragma unroll
        for (int nt = 0; nt < 8; ++nt) {
            int r = crow + m0 + mt * 16 + lr;
            int c = ccol + n0 + nt * 8 + lc;
            *reinterpret_cast<float2*>(&C[(size_t)r * HH + c]) =
                make_float2(acc[mt][nt][0], acc[mt][nt][1]);
            *reinterpret_cast<float2*>(&C[(size_t)(r + 8) * HH + c]) =
                make_float2(acc[mt][nt][2], acc[mt][nt][3]);
        }
}

// ---------------------------------------------------------------------------
extern "C" void kernel_launch(void* const* d_in, const int* in_sizes, int n_in,
                              void* d_out, int out_size) {
    const float* x = (const float*)d_in[0];   // [4,2048,1024]
    const float* W = (const float*)d_in[1];   // [1024,1024]
    float* out = (float*)d_out;               // [4,2048,1024]

    cudaFuncSetAttribute(gemm_mma, cudaFuncAttributeMaxDynamicSharedMemorySize,
                         GEMM_SMEM);

    gram_mma<<<dim3(BB * NH, SPL), 256>>>(x);
    combine_mma<<<dim3(BB * NH, 4), 256>>>(W);
    gemm_mma<<<dim3(HH / 128, SS / 128, BB), 128, GEMM_SMEM>>>(out);
}

// round 17
// speedup vs baseline: 1.0670x; 1.0386x over previous
#include <cuda_runtime.h>
#include <cuda_fp16.h>
#include <cstdint>

// Problem constants
constexpr int BB  = 4;
constexpr int SS  = 2048;
constexpr int HH  = 1024;
constexpr int NH  = 16;
constexpr int HD  = 64;
constexpr int SPL = 8;

// Scratch (static device globals — allowed)
__device__ float g_Gpart[SPL][BB * NH][HD][HD];  // 8 MB
__device__ __half g_Vt[BB][HH][HH];              // 8.4 MB: Vt[n][k]
__device__ __half g_Xh[BB][SS][HH];              // 16.8 MB: x rounded to fp16

// ---------------------------------------------------------------------------
// helpers
// ---------------------------------------------------------------------------
__device__ __forceinline__ void mma16816(float* c, const uint32_t* a, const uint32_t* b) {
    asm volatile(
        "mma.sync.aligned.m16n8k16.row.col.f32.f16.f16.f32 "
        "{%0,%1,%2,%3}, {%4,%5,%6,%7}, {%8,%9}, {%0,%1,%2,%3};"
        : "+f"(c[0]), "+f"(c[1]), "+f"(c[2]), "+f"(c[3])
        : "r"(a[0]), "r"(a[1]), "r"(a[2]), "r"(a[3]), "r"(b[0]), "r"(b[1]));
}
__device__ __forceinline__ void ldsm4(uint32_t* r, uint32_t saddr) {
    asm volatile("ldmatrix.sync.aligned.m8n8.x4.shared.b16 {%0,%1,%2,%3}, [%4];"
                 : "=r"(r[0]), "=r"(r[1]), "=r"(r[2]), "=r"(r[3]) : "r"(saddr));
}
__device__ __forceinline__ void ldsm4t(uint32_t* r, uint32_t saddr) {
    asm volatile("ldmatrix.sync.aligned.m8n8.x4.trans.shared.b16 {%0,%1,%2,%3}, [%4];"
                 : "=r"(r[0]), "=r"(r[1]), "=r"(r[2]), "=r"(r[3]) : "r"(saddr));
}
__device__ __forceinline__ void cpasync16(uint32_t dst, const void* src) {
    asm volatile("cp.async.cg.shared.global [%0], [%1], 16;" :: "r"(dst), "l"(src));
}
#define CP_COMMIT() asm volatile("cp.async.commit_group;" ::: "memory")
#define CP_WAIT1()  asm volatile("cp.async.wait_group 1;" ::: "memory")

// ---------------------------------------------------------------------------
// Kernel 1: partial Gram via HMMA (hi/lo split, 3 passes) + emit g_Xh (fp16 hi)
//   batched grid (BB*NH, SPL); cross-sub LDG software pipeline.
// ---------------------------------------------------------------------------
constexpr int GP = 72;   // smem row pitch (halves)

__global__ void __launch_bounds__(256) gram_mma(const float* __restrict__ x) {
    __shared__ __align__(16) __half Xhs[64][GP];
    __shared__ __align__(16) __half Xls[64][GP];

    const int bh    = blockIdx.x;
    const int chunk = blockIdx.y;
    const int b = bh / NH, h = bh % NH;
    const float* Xb = x + (size_t)b * SS * HH + h * HD;
    const int s0 = chunk * (SS / SPL);

    const int t = threadIdx.x, lane = t & 31, w = t >> 5;
    const int lr8 = lane & 7, g = lane >> 3;

    const int m0 = (w & 3) * 16;
    const int nb = (w >> 2) * 32;

    float acc[4][4] = {};

    uint32_t hbase = (uint32_t)__cvta_generic_to_shared(&Xhs[0][0]);
    uint32_t lbase = (uint32_t)__cvta_generic_to_shared(&Xls[0][0]);
    const uint32_t aoff = (uint32_t)((((g & 2) ? 8 : 0) + lr8) * GP + m0 + ((g & 1) ? 8 : 0)) * 2;
    const uint32_t boff0 = (uint32_t)((((g & 1) ? 8 : 0) + lr8) * GP + nb + ((g & 2) ? 8 : 0)) * 2;
    const uint32_t boff1 = boff0 + 16 * 2;

    const int ldr = t >> 4, ldc = t & 15;   // row 0..15 (x4 groups), 16B col 0..15

    float4 vv[4];
#pragma unroll
    for (int q = 0; q < 4; ++q) {
        int srow = s0 + q * 16 + ldr;
        vv[q] = *reinterpret_cast<const float4*>(&Xb[(size_t)srow * HH + ldc * 4]);
    }

    for (int sub = 0; sub < 4; ++sub) {
        // convert current sub's registers into smem (+ emit g_Xh)
#pragma unroll
        for (int q = 0; q < 4; ++q) {
            int r = q * 16 + ldr;
            int srow = s0 + sub * 64 + r;
            float4 v = vv[q];
            __half hx = __float2half_rn(v.x), hy = __float2half_rn(v.y);
            __half hz = __float2half_rn(v.z), hw = __float2half_rn(v.w);
            __half lx = __float2half_rn(v.x - __half2float(hx));
            __half ly = __float2half_rn(v.y - __half2float(hy));
            __half lz = __float2half_rn(v.z - __half2float(hz));
            __half lw = __float2half_rn(v.w - __half2float(hw));
            __half2 p0 = __halves2half2(hx, hy), p1 = __halves2half2(hz, hw);
            __half2* dh = reinterpret_cast<__half2*>(&Xhs[r][ldc * 4]);
            dh[0] = p0; dh[1] = p1;
            __half2* dl = reinterpret_cast<__half2*>(&Xls[r][ldc * 4]);
            dl[0] = __halves2half2(lx, ly); dl[1] = __halves2half2(lz, lw);
            __half2* gx = reinterpret_cast<__half2*>(&g_Xh[b][srow][h * HD + ldc * 4]);
            gx[0] = p0; gx[1] = p1;
        }
        __syncthreads();

        // prefetch next sub NOW — latency hides under the MMA loop below
        if (sub < 3) {
#pragma unroll
            for (int q = 0; q < 4; ++q) {
                int srow = s0 + (sub + 1) * 64 + q * 16 + ldr;
                vv[q] = *reinterpret_cast<const float4*>(&Xb[(size_t)srow * HH + ldc * 4]);
            }
        }

#pragma unroll
        for (int kk = 0; kk < 64; kk += 16) {
            const uint32_t kb = (uint32_t)(kk * GP * 2);
            uint32_t ah[4], al[4], bh0[4], bh1[4], bl0[4], bl1[4];
            ldsm4t(ah,  hbase + kb + aoff);
            ldsm4t(al,  lbase + kb + aoff);
            ldsm4t(bh0, hbase + kb + boff0);
            ldsm4t(bh1, hbase + kb + boff1);
            ldsm4t(bl0, lbase + kb + boff0);
            ldsm4t(bl1, lbase + kb + boff1);
#pragma unroll
            for (int nt = 0; nt < 4; ++nt) {
                const uint32_t* bh_ = (nt < 2) ? bh0 : bh1;
                const uint32_t* bl_ = (nt < 2) ? bl0 : bl1;
                uint32_t bhf[2] = {bh_[(nt & 1) * 2], bh_[(nt & 1) * 2 + 1]};
                uint32_t blf[2] = {bl_[(nt & 1) * 2], bl_[(nt & 1) * 2 + 1]};
                mma16816(acc[nt], ah, bhf);
                mma16816(acc[nt], ah, blf);
                mma16816(acc[nt], al, bhf);
            }
        }
        __syncthreads();
    }

    const int lr = lane >> 2, lc = (lane & 3) * 2;
#pragma unroll
    for (int nt = 0; nt < 4; ++nt) {
        int n = nb + nt * 8 + lc;
        *reinterpret_cast<float2*>(&g_Gpart[chunk][bh][m0 + lr][n]) =
            make_float2(acc[nt][0], acc[nt][1]);
        *reinterpret_cast<float2*>(&g_Gpart[chunk][bh][m0 + lr + 8][n]) =
            make_float2(acc[nt][2], acc[nt][3]);
    }
}

// ---------------------------------------------------------------------------
// Kernel 2: combine via HMMA -> Vt[n][k] fp16 ; batched: grid (BB*NH, 4)
// ---------------------------------------------------------------------------
__global__ void __launch_bounds__(256) combine_mma(const float* __restrict__ W) {
    __shared__ __align__(16) __half Gh[64][GP], Gl[64][GP];
    __shared__ __align__(16) __half Wh[64][GP], Wl[64][GP];

    const int bh = blockIdx.x, ic = blockIdx.y;
    const int b = bh / NH, h = bh % NH;
    const int t = threadIdx.x, lane = t & 31, w = t >> 5;
    const int m0 = (w & 1) * 32;
    const int n0 = (w >> 1) * 16;

    for (int idx = t; idx < 64 * 64; idx += 256) {
        int e = idx >> 6, d = idx & 63;
        float s = 0.f;
#pragma unroll
        for (int p = 0; p < SPL; ++p) s += g_Gpart[p][bh][e][d];
        __half hi = __float2half_rn(s);
        Gh[e][d] = hi;
        Gl[e][d] = __float2half_rn(s - __half2float(hi));
    }

    const int lr8 = lane & 7, g = lane >> 3;
    const uint32_t ghb = (uint32_t)__cvta_generic_to_shared(&Gh[0][0]);
    const uint32_t glb = (uint32_t)__cvta_generic_to_shared(&Gl[0][0]);
    const uint32_t whb = (uint32_t)__cvta_generic_to_shared(&Wh[0][0]);
    const uint32_t wlb = (uint32_t)__cvta_generic_to_shared(&Wl[0][0]);
    const uint32_t aoff0 = (uint32_t)((((g & 2) ? 8 : 0) + lr8) * GP + m0 + ((g & 1) ? 8 : 0)) * 2;
    const uint32_t aoff1 = aoff0 + 16 * 2;
    const uint32_t boff  = (uint32_t)((((g & 1) ? 8 : 0) + lr8) * GP + n0 + ((g & 2) ? 8 : 0)) * 2;

    const int lr = lane >> 2, lc = (lane & 3) * 2;
    __syncthreads();

    for (int sub = 0; sub < 4; ++sub) {
        const int i0 = ic * 256 + sub * 64;
        for (int idx = t; idx < 64 * 64; idx += 256) {
            int e = idx >> 6, i = idx & 63;
            float wv = W[(size_t)(h * HD + e) * HH + i0 + i] * 8192.f;
            __half hi = __float2half_rn(wv);
            Wh[e][i] = hi;
            Wl[e][i] = __float2half_rn(wv - __half2float(hi));
        }
        __syncthreads();

        float acc[2][2][4] = {};
#pragma unroll
        for (int kk = 0; kk < 64; kk += 16) {
            const uint32_t kb = (uint32_t)(kk * GP * 2);
            uint32_t a0h[4], a0l[4], a1h[4], a1l[4], bwh[4], bwl[4];
            ldsm4t(a0h, ghb + kb + aoff0);
            ldsm4t(a0l, glb + kb + aoff0);
            ldsm4t(a1h, ghb + kb + aoff1);
            ldsm4t(a1l, glb + kb + aoff1);
            ldsm4t(bwh, whb + kb + boff);
            ldsm4t(bwl, wlb + kb + boff);
#pragma unroll
            for (int nt = 0; nt < 2; ++nt) {
                uint32_t bhf[2] = {bwh[nt * 2], bwh[nt * 2 + 1]};
                uint32_t blf[2] = {bwl[nt * 2], bwl[nt * 2 + 1]};
                mma16816(acc[0][nt], a0h, bhf);
                mma16816(acc[0][nt], a0h, blf);
                mma16816(acc[0][nt], a0l, bhf);
                mma16816(acc[1][nt], a1h, bhf);
                mma16816(acc[1][nt], a1h, blf);
                mma16816(acc[1][nt], a1l, bhf);
            }
        }

        const float is = 1.f / 8192.f;
#pragma unroll
        for (int mt = 0; mt < 2; ++mt)
#pragma unroll
            for (int nt = 0; nt < 2; ++nt) {
                int d = m0 + mt * 16 + lr;
                int gi = i0 + n0 + nt * 8 + lc;
                __half2 v01 = __floats2half2_rn(acc[mt][nt][0] * is, acc[mt][nt][1] * is);
                __half2 v23 = __floats2half2_rn(acc[mt][nt][2] * is, acc[mt][nt][3] * is);
                *reinterpret_cast<__half2*>(&g_Vt[b][h * HD + d][gi]) = v01;
                *reinterpret_cast<__half2*>(&g_Vt[b][h * HD + d + 8][gi]) = v23;
            }
        __syncthreads();
    }
}

// ---------------------------------------------------------------------------
// Kernel 3: pure-fp16 HMMA GEMM — KT=64, 3-stage ring, conflict-free cp.async
//   4 warps x (64x64), CTA 128x128, 110.6KB smem, 2 CTA/SM
// ---------------------------------------------------------------------------
constexpr int KT    = 64;
constexpr int PITCH = 72;                 // halves per smem row
constexpr int OPH   = 128 * PITCH;        // halves per operand tile
constexpr int STH   = 2 * OPH;            // halves per stage
constexpr int NST   = 3;
constexpr int GEMM_SMEM = NST * STH * 2;  // 110592 bytes

__global__ void __launch_bounds__(128, 2) gemm_mma(float* __restrict__ Out) {
    extern __shared__ __half sm[];
    const int t = threadIdx.x, lane = t & 31, wid = t >> 5;
    const int b = blockIdx.z;
    const int crow = blockIdx.y * 128, ccol = blockIdx.x * 128;
    const __half* Ag = &g_Xh[b][0][0];
    const __half* Bg = &g_Vt[b][0][0];

    const uint32_t smu = (uint32_t)__cvta_generic_to_shared(sm);

    const int m0 = (wid & 1) * 64;
    const int n0 = (wid >> 1) * 64;
    const int lr8 = lane & 7, g = lane >> 3;

    uint32_t aoffb[4], boffb[4];
#pragma unroll
    for (int mt = 0; mt < 4; ++mt)
        aoffb[mt] = (uint32_t)(((m0 + mt * 16 + ((g & 1) ? 8 : 0) + lr8) * PITCH
                                + ((g & 2) ? 8 : 0)) * 2);
#pragma unroll
    for (int j = 0; j < 4; ++j)
        boffb[j] = (uint32_t)(((n0 + j * 16 + ((g & 1) ? 8 : 0) + lr8) * PITCH
                               + ((g & 2) ? 8 : 0)) * 2);

    // conflict-free cp.async mapping: row = q*16 + t>>3, 16B chunk = t&7.
    // Within a warp: 4 rows x 8 chunks -> every 16B bank-group covered exactly
    // 4x = minimum 4 phases, no excess conflicts.
    const int cpr = t >> 3, cpc = t & 7;
    const __half* aSrc = Ag + (size_t)(crow + cpr) * HH + cpc * 8;
    const __half* bSrc = Bg + (size_t)(ccol + cpr) * HH + cpc * 8;
    const uint32_t aDst = smu + (uint32_t)((cpr * PITCH + cpc * 8) * 2);
    const uint32_t bDst = aDst + OPH * 2;

    float acc[4][8][4];
#pragma unroll
    for (int mt = 0; mt < 4; ++mt)
#pragma unroll
        for (int nt = 0; nt < 8; ++nt)
#pragma unroll
            for (int j = 0; j < 4; ++j) acc[mt][nt][j] = 0.f;

#define ISSUE_STAGE(st, buf)                                                    \
    do {                                                                        \
        const int k0 = (st) * KT;                                               \
        const uint32_t sb = (uint32_t)((buf) * STH * 2);                        \
        _Pragma("unroll")                                                       \
        for (int q = 0; q < 8; ++q) {                                           \
            cpasync16(aDst + sb + q * 16 * PITCH * 2,                           \
                      aSrc + (size_t)q * 16 * HH + k0);                         \
            cpasync16(bDst + sb + q * 16 * PITCH * 2,                           \
                      bSrc + (size_t)q * 16 * HH + k0);                         \
        }                                                                       \
    } while (0)

    ISSUE_STAGE(0, 0); CP_COMMIT();
    ISSUE_STAGE(1, 1); CP_COMMIT();

    const int NSTAGES = HH / KT;   // 16
    for (int st = 0; st < NSTAGES; ++st) {
        CP_WAIT1();
        __syncthreads();

        // issue-early into (st+2)%3 == (st-1)%3 (reads finished per sync above)
        if (st + 2 < NSTAGES) ISSUE_STAGE(st + 2, (st + 2) % 3);
        CP_COMMIT();

        const uint32_t baseA = smu + (uint32_t)((st % 3) * STH * 2);
        const uint32_t baseB = baseA + OPH * 2;
#pragma unroll
        for (int kk = 0; kk < KT; kk += 16) {
            const uint32_t kb = (uint32_t)(kk * 2);
            uint32_t af[4][4], bf[4][4];
#pragma unroll
            for (int mt = 0; mt < 4; ++mt) ldsm4(af[mt], baseA + aoffb[mt] + kb);
#pragma unroll
            for (int j = 0; j < 4; ++j)    ldsm4(bf[j],  baseB + boffb[j] + kb);
#pragma unroll
            for (int mt = 0; mt < 4; ++mt)
#pragma unroll
                for (int nt = 0; nt < 8; ++nt) {
                    uint32_t bb[2] = {bf[nt >> 1][(nt & 1) ? 1 : 0],
                                      bf[nt >> 1][(nt & 1) ? 3 : 2]};
                    mma16816(acc[mt][nt], af[mt], bb);
                }
        }
    }

    // Epilogue
    const int lr = lane >> 2, lc = (lane & 3) * 2;
    float* C = Out + (size_t)b * SS * HH;
#pragma unroll
    for (int mt = 0; mt < 4; ++mt)
#pragma unroll
        for (int nt = 0; nt < 8; ++nt) {
            int r = crow + m0 + mt * 16 + lr;
            int c = ccol + n0 + nt * 8 + lc;
            *reinterpret_cast<float2*>(&C[(size_t)r * HH + c]) =
                make_float2(acc[mt][nt][0], acc[mt][nt][1]);
            *reinterpret_cast<float2*>(&C[(size_t)(r + 8) * HH + c]) =
                make_float2(acc[mt][nt][2], acc[mt][nt][3]);
        }
}

// ---------------------------------------------------------------------------
extern "C" void kernel_launch(void* const* d_in, const int* in_sizes, int n_in,
                              void* d_out, int out_size) {
    const float* x = (const float*)d_in[0];   // [4,2048,1024]
    const float* W = (const float*)d_in[1];   // [1024,1024]
    float* out = (float*)d_out;               // [4,2048,1024]

    cudaFuncSetAttribute(gemm_mma, cudaFuncAttributeMaxDynamicSharedMemorySize,
                         GEMM_SMEM);

    gram_mma<<<dim3(BB * NH, SPL), 256>>>(x);
    combine_mma<<<dim3(BB * NH, 4), 256>>>(W);
    gemm_mma<<<dim3(HH / 128, SS / 128, BB), 128, GEMM_SMEM>>>(out);
}